// round 14
// baseline (speedup 1.0000x reference)
#include <cuda_runtime.h>
#include <cuda_fp16.h>
#include <stdint.h>

#define T 1024
#define Hd 1024
#define Id 1024
#define NE 16
#define TOPK 4

// ---------------- scratch (no runtime allocation allowed) ----------------
__device__ __align__(16) __half g_xn[T * Hd];             // normed activations, fp16
__device__ int   g_cnt[NE];
__device__ int   g_perm[NE * T];
__device__ float g_gate[NE * T];
__device__ int   g_flag;                                  // counts-zeroed flag
__device__ int   g_fin;                                   // norm blocks finished
__device__ __align__(16) __half g_s[(size_t)NE * T * Id]; // swiglu output, fp16

// ---------------- shared memory map ----------------
#define OFF_A    0
#define OFF_B16  40960
#define OFF_TOK  (40960 + 17408)            // 58368
#define OFF_GATE (58368 + 512)
#define DYN_SMEM (58368 + 1024)             // 59392

// ---------------- kernel 1: RMSNorm + router + residual (warp-per-token) ----
// grid 128, block 256 (8 warps = 8 tokens). Block 0 zeroes counters, raises
// g_flag; all blocks spin on it before their atomicAdds. Last finisher resets
// flag/fin so every graph replay starts from identical state.
__global__ __launch_bounds__(256) void k_norm_route(
    const float* __restrict__ x, const float* __restrict__ ns,
    const float* __restrict__ wg, const float* __restrict__ bg,
    float* __restrict__ out)
{
    if (blockIdx.x == 0 && threadIdx.x < 32) {
        if (threadIdx.x < NE) g_cnt[threadIdx.x] = 0;
        __threadfence();
        __syncwarp();
        if (threadIdx.x == 0) atomicExch(&g_flag, 1);
    }

    int warp = threadIdx.x >> 5, lane = threadIdx.x & 31;
    int t = blockIdx.x * 8 + warp;

    const float4* xr = (const float4*)(x + (size_t)t * Hd);
    float4 xv[8];
    #pragma unroll
    for (int j = 0; j < 8; j++) xv[j] = xr[j * 32 + lane];

    float ss = 0.f;
    #pragma unroll
    for (int j = 0; j < 8; j++)
        ss += xv[j].x * xv[j].x + xv[j].y * xv[j].y + xv[j].z * xv[j].z + xv[j].w * xv[j].w;
    #pragma unroll
    for (int o = 16; o; o >>= 1) ss += __shfl_xor_sync(0xffffffffu, ss, o);
    float rms = rsqrtf(ss * (1.0f / Hd) + 1e-5f);

    float4* orow = (float4*)(out + (size_t)t * Hd);
    #pragma unroll
    for (int j = 0; j < 8; j++) orow[j * 32 + lane] = xv[j];

    float acc[NE];
    #pragma unroll
    for (int e = 0; e < NE; e++) acc[e] = 0.f;

    #pragma unroll
    for (int j = 0; j < 8; j++) {
        int h = (j * 32 + lane) * 4;
        float4 nsv = ((const float4*)ns)[j * 32 + lane];
        float n0 = xv[j].x * rms * nsv.x;
        float n1 = xv[j].y * rms * nsv.y;
        float n2 = xv[j].z * rms * nsv.z;
        float n3 = xv[j].w * rms * nsv.w;
        __half2 p0 = __floats2half2_rn(n0, n1);
        __half2 p1 = __floats2half2_rn(n2, n3);
        *(uint2*)(g_xn + (size_t)t * Hd + h) =
            make_uint2(*(uint32_t*)&p0, *(uint32_t*)&p1);
        float nv[4] = {n0, n1, n2, n3};
        #pragma unroll
        for (int v = 0; v < 4; v++) {
            const float4* wrow = (const float4*)(wg + (size_t)(h + v) * NE);
            float4 w0 = wrow[0], w1 = wrow[1], w2 = wrow[2], w3 = wrow[3];
            acc[0]  += nv[v] * w0.x;  acc[1]  += nv[v] * w0.y;
            acc[2]  += nv[v] * w0.z;  acc[3]  += nv[v] * w0.w;
            acc[4]  += nv[v] * w1.x;  acc[5]  += nv[v] * w1.y;
            acc[6]  += nv[v] * w1.z;  acc[7]  += nv[v] * w1.w;
            acc[8]  += nv[v] * w2.x;  acc[9]  += nv[v] * w2.y;
            acc[10] += nv[v] * w2.z;  acc[11] += nv[v] * w2.w;
            acc[12] += nv[v] * w3.x;  acc[13] += nv[v] * w3.y;
            acc[14] += nv[v] * w3.z;  acc[15] += nv[v] * w3.w;
        }
    }
    #pragma unroll
    for (int o = 16; o; o >>= 1)
        #pragma unroll
        for (int e = 0; e < NE; e++) acc[e] += __shfl_xor_sync(0xffffffffu, acc[e], o);

    if (lane == 0) {
        float logits[NE];
        #pragma unroll
        for (int e = 0; e < NE; e++) logits[e] = acc[e] + bg[e];
        float vals[TOPK]; int idx[TOPK];
        unsigned used = 0;
        for (int k = 0; k < TOPK; k++) {
            float best = -1e30f; int bi = 0;
            #pragma unroll
            for (int e = 0; e < NE; e++)
                if (!((used >> e) & 1u) && logits[e] > best) { best = logits[e]; bi = e; }
            used |= 1u << bi; vals[k] = best; idx[k] = bi;
        }
        float ex[TOPK], den = 0.f;
        #pragma unroll
        for (int k = 0; k < TOPK; k++) { ex[k] = __expf(vals[k] - vals[0]); den += ex[k]; }
        float inv = 1.f / den;
        // wait until counters are zeroed (block 0 raises g_flag)
        {
            volatile int* fp = &g_flag;
            while (*fp == 0) { }
        }
        #pragma unroll
        for (int k = 0; k < TOPK; k++) {
            int e = idx[k];
            int pos = atomicAdd(&g_cnt[e], 1);
            g_perm[e * T + pos] = t;
            g_gate[e * T + pos] = ex[k] * inv;
        }
    }
    // last block to finish resets flag/fin for the next replay
    __syncthreads();
    if (threadIdx.x == 0) {
        __threadfence();
        int f = atomicAdd(&g_fin, 1);
        if (f == gridDim.x - 1) { g_flag = 0; g_fin = 0; __threadfence(); }
    }
}

// ---------------- helpers ----------------
__device__ __forceinline__ void mma16816(float* c, const uint32_t* a, const uint32_t* b) {
    asm volatile(
        "mma.sync.aligned.m16n8k16.row.col.f32.f16.f16.f32 "
        "{%0,%1,%2,%3}, {%4,%5,%6,%7}, {%8,%9}, {%0,%1,%2,%3};\n"
        : "+f"(c[0]), "+f"(c[1]), "+f"(c[2]), "+f"(c[3])
        : "r"(a[0]), "r"(a[1]), "r"(a[2]), "r"(a[3]), "r"(b[0]), "r"(b[1]));
}
__device__ __forceinline__ void cpa16(void* dst, const void* src, int sz) {
    uint32_t d = (uint32_t)__cvta_generic_to_shared(dst);
    asm volatile("cp.async.cg.shared.global [%0], [%1], 16, %2;\n" :: "r"(d), "l"(src), "r"(sz));
}
__device__ __forceinline__ void cpa_commit() { asm volatile("cp.async.commit_group;\n"); }
__device__ __forceinline__ void cpa_wait2()  { asm volatile("cp.async.wait_group 2;\n"); }
__device__ __forceinline__ uint32_t h2pack(float a, float b) {
    __half2 h = __floats2half2_rn(a, b);
    return *(uint32_t*)&h;
}
__device__ __forceinline__ void ldsm4(uint32_t* r, const void* p) {
    uint32_t addr = (uint32_t)__cvta_generic_to_shared(p);
    asm volatile("ldmatrix.sync.aligned.m8n8.x4.shared.b16 {%0,%1,%2,%3}, [%4];"
        : "=r"(r[0]), "=r"(r[1]), "=r"(r[2]), "=r"(r[3]) : "r"(addr));
}
__device__ __forceinline__ void ldsm4t(uint32_t* r, const void* p) {
    uint32_t addr = (uint32_t)__cvta_generic_to_shared(p);
    asm volatile("ldmatrix.sync.aligned.m8n8.x4.trans.shared.b16 {%0,%1,%2,%3}, [%4];"
        : "=r"(r[0]), "=r"(r[1]), "=r"(r[2]), "=r"(r[3]) : "r"(addr));
}

struct SmemView {
    __half (*As)[128][40];
    __half (*B16)[32][136];
    int* rowTok;
    float* rowGate;
};
__device__ __forceinline__ SmemView smview(char* base) {
    SmemView s;
    s.As     = (__half(*)[128][40])(base + OFF_A);
    s.B16    = (__half(*)[32][136])(base + OFF_B16);
    s.rowTok = (int*)(base + OFF_TOK);
    s.rowGate= (float*)(base + OFF_GATE);
    return s;
}

__device__ __forceinline__ void ldgB(float4* rF, const float* __restrict__ w,
                                     int ld, int k0, int nBase, int tid) {
    int ck = tid >> 3, l = tid & 7;
    const float* row = w + (size_t)(k0 + ck) * ld + nBase + l * 4;
    #pragma unroll
    for (int j = 0; j < 4; j++) rF[j] = *(const float4*)(row + j * 32);
}
__device__ __forceinline__ void stsB(SmemView& sv, int buf, const float4* rF, int tid) {
    int ck = tid >> 3, l = tid & 7;
    #pragma unroll
    for (int j = 0; j < 4; j++) {
        uint2 p = make_uint2(h2pack(rF[j].x, rF[j].y), h2pack(rF[j].z, rF[j].w));
        *(uint2*)&sv.B16[buf][ck][l * 4 + j * 32] = p;
    }
}

// ---------------- kernel 2: grouped GEMM1 + swiglu ----------------
// grid (nTile=16, mTile=4, expert=16), block 256; warp grid 4x2 (32m x 64n)
__global__ __launch_bounds__(256, 2) void k_ffn1(
    const float* __restrict__ w1, const float* __restrict__ b1)
{
    extern __shared__ char smbase[];
    SmemView sv = smview(smbase);

    int e = blockIdx.z;
    int cnt = g_cnt[e];
    int mBase = blockIdx.y * 128;
    if (mBase >= cnt) return;
    int nBase = blockIdx.x * 128;
    int validRows = cnt - mBase; if (validRows > 128) validRows = 128;

    int tid = threadIdx.x;
    if (tid < 128) {
        int slot = mBase + tid;
        sv.rowTok[tid] = (slot < cnt) ? g_perm[e * T + slot] : -1;
    }
    __syncthreads();

    int lane = tid & 31, warp = tid >> 5;
    int wm = warp >> 1, wn = warp & 1;
    bool warpLive = (wm * 32) < validRows;

    float acc[2][8][4];
    #pragma unroll
    for (int mf = 0; mf < 2; mf++)
        #pragma unroll
        for (int nf = 0; nf < 8; nf++)
            #pragma unroll
            for (int i = 0; i < 4; i++) acc[mf][nf][i] = 0.f;

    auto issueA = [&](int s) {
        int k0 = s * 32;
        #pragma unroll
        for (int c = 0; c < 2; c++) {
            int ch = tid + c * 256;
            int row = ch >> 2, col = (ch & 3) * 8;
            int tok = sv.rowTok[row];
            if (tok >= 0) cpa16(&sv.As[s & 3][row][col], g_xn + (size_t)tok * Hd + k0 + col, 16);
            else          cpa16(&sv.As[s & 3][row][col], g_xn, 0);
        }
    };

    const int LD = 2 * Id;
    float4 rF[4];

    issueA(0); cpa_commit();
    issueA(1); cpa_commit();
    issueA(2); cpa_commit();
    ldgB(rF, w1 + (size_t)e * Hd * LD, LD, 0, nBase, tid);
    stsB(sv, 0, rF, tid);
    ldgB(rF, w1 + (size_t)e * Hd * LD, LD, 32, nBase, tid);

    const int KT = Hd / 32;
    for (int it = 0; it < KT; it++) {
        cpa_wait2();
        __syncthreads();
        if (it + 1 < KT) stsB(sv, (it + 1) & 1, rF, tid);
        if (warpLive) {
            #pragma unroll
            for (int kk = 0; kk < 32; kk += 16) {
                uint32_t a[2][4], b[8][2];
                #pragma unroll
                for (int mf = 0; mf < 2; mf++) {
                    int r = wm * 32 + mf * 16 + (lane & 15);
                    ldsm4(a[mf], &sv.As[it & 3][r][kk + (lane >> 4) * 8]);
                }
                #pragma unroll
                for (int pair = 0; pair < 4; pair++) {
                    int m = lane >> 3, r = lane & 7;
                    uint32_t rr[4];
                    ldsm4t(rr, &sv.B16[it & 1][kk + (m & 1) * 8 + r][wn * 64 + pair * 16 + (m >> 1) * 8]);
                    b[pair * 2 + 0][0] = rr[0]; b[pair * 2 + 0][1] = rr[1];
                    b[pair * 2 + 1][0] = rr[2]; b[pair * 2 + 1][1] = rr[3];
                }
                #pragma unroll
                for (int mf = 0; mf < 2; mf++)
                    #pragma unroll
                    for (int nf = 0; nf < 8; nf++)
                        mma16816(acc[mf][nf], a[mf], b[nf]);
            }
        }
        if (it + 2 < KT) ldgB(rF, w1 + (size_t)e * Hd * LD, LD, (it + 2) * 32, nBase, tid);
        if (it + 3 < KT) issueA(it + 3);
        cpa_commit();
    }

    // ---- epilogue: swiglu -> smem staging -> coalesced g_s ----
    __half (*Ss)[72] = (__half(*)[72])(smbase + OFF_A);
    __syncthreads();
    if (warpLive) {
        int g = lane >> 2, tg = lane & 3;
        #pragma unroll
        for (int mf = 0; mf < 2; mf++) {
            #pragma unroll
            for (int nf = 0; nf < 8; nf++) {
                int ncol = nBase + wn * 64 + nf * 8 + tg * 2;   // even
                float ba = b1[e * (2 * Id) + ncol];
                float bb = b1[e * (2 * Id) + ncol + 1];
                int sl = wn * 32 + nf * 4 + tg;                 // local scol 0..63
                #pragma unroll
                for (int h = 0; h < 2; h++) {
                    int row = wm * 32 + mf * 16 + g + h * 8;
                    float av = acc[mf][nf][h * 2 + 0] + ba;
                    float bv = acc[mf][nf][h * 2 + 1] + bb;
                    av = fminf(av, 7.0f);
                    bv = fminf(fmaxf(bv, -7.0f), 7.0f);
                    float sig = __frcp_rn(1.f + __expf(-1.702f * av));
                    Ss[row][sl] = __float2half(av * sig * (bv + 1.f));
                }
            }
        }
    }
    __syncthreads();
    {
        int r0 = tid >> 3, cl = (tid & 7) * 8;
        #pragma unroll
        for (int p = 0; p < 4; p++) {
            int row = p * 32 + r0;
            int slot = mBase + row;
            if (slot < cnt) {
                uint4 v = *(uint4*)&Ss[row][cl];
                *(uint4*)(g_s + ((size_t)(e * T + slot)) * Id + (nBase >> 1) + cl) = v;
            }
        }
    }
}

// ---------------- kernel 3: grouped GEMM2 + gated scatter ----------------
// grid (nTile=8, mTile=4, expert=16), block 256; warp grid 4x2
__global__ __launch_bounds__(256, 2) void k_ffn2(
    const float* __restrict__ w2, const float* __restrict__ b2, float* __restrict__ out)
{
    extern __shared__ char smbase[];
    SmemView sv = smview(smbase);

    int e = blockIdx.z;
    int cnt = g_cnt[e];
    int mBase = blockIdx.y * 128;
    if (mBase >= cnt) return;
    int nBase = blockIdx.x * 128;
    int validRows = cnt - mBase; if (validRows > 128) validRows = 128;

    int tid = threadIdx.x;
    if (tid < 128) {
        int slot = mBase + tid;
        if (slot < cnt) { sv.rowTok[tid] = g_perm[e * T + slot]; sv.rowGate[tid] = g_gate[e * T + slot]; }
        else            { sv.rowTok[tid] = -1;                   sv.rowGate[tid] = 0.f; }
    }
    __syncthreads();

    int lane = tid & 31, warp = tid >> 5;
    int wm = warp >> 1, wn = warp & 1;
    bool warpLive = (wm * 32) < validRows;

    float acc[2][8][4];
    #pragma unroll
    for (int mf = 0; mf < 2; mf++)
        #pragma unroll
        for (int nf = 0; nf < 8; nf++)
            #pragma unroll
            for (int i = 0; i < 4; i++) acc[mf][nf][i] = 0.f;

    auto issueA = [&](int s) {
        int k0 = s * 32;
        #pragma unroll
        for (int c = 0; c < 2; c++) {
            int ch = tid + c * 256;
            int row = ch >> 2, col = (ch & 3) * 8;
            int valid = (row < validRows) ? 16 : 0;
            const __half* src = g_s + ((size_t)(e * T + mBase + row)) * Id + k0 + col;
            cpa16(&sv.As[s & 3][row][col], src, valid);
        }
    };

    float4 rF[4];

    issueA(0); cpa_commit();
    issueA(1); cpa_commit();
    issueA(2); cpa_commit();
    ldgB(rF, w2 + (size_t)e * Id * Hd, Hd, 0, nBase, tid);
    stsB(sv, 0, rF, tid);
    ldgB(rF, w2 + (size_t)e * Id * Hd, Hd, 32, nBase, tid);

    const int KT = Id / 32;
    for (int it = 0; it < KT; it++) {
        cpa_wait2();
        __syncthreads();
        if (it + 1 < KT) stsB(sv, (it + 1) & 1, rF, tid);
        if (warpLive) {
            #pragma unroll
            for (int kk = 0; kk < 32; kk += 16) {
                uint32_t a[2][4], b[8][2];
                #pragma unroll
                for (int mf = 0; mf < 2; mf++) {
                    int r = wm * 32 + mf * 16 + (lane & 15);
                    ldsm4(a[mf], &sv.As[it & 3][r][kk + (lane >> 4) * 8]);
                }
                #pragma unroll
                for (int pair = 0; pair < 4; pair++) {
                    int m = lane >> 3, r = lane & 7;
                    uint32_t rr[4];
                    ldsm4t(rr, &sv.B16[it & 1][kk + (m & 1) * 8 + r][wn * 64 + pair * 16 + (m >> 1) * 8]);
                    b[pair * 2 + 0][0] = rr[0]; b[pair * 2 + 0][1] = rr[1];
                    b[pair * 2 + 1][0] = rr[2]; b[pair * 2 + 1][1] = rr[3];
                }
                #pragma unroll
                for (int mf = 0; mf < 2; mf++)
                    #pragma unroll
                    for (int nf = 0; nf < 8; nf++)
                        mma16816(acc[mf][nf], a[mf], b[nf]);
            }
        }
        if (it + 2 < KT) ldgB(rF, w2 + (size_t)e * Id * Hd, Hd, (it + 2) * 32, nBase, tid);
        if (it + 3 < KT) issueA(it + 3);
        cpa_commit();
    }

    if (warpLive) {
        int g = lane >> 2, tg = lane & 3;
        #pragma unroll
        for (int mf = 0; mf < 2; mf++) {
            #pragma unroll
            for (int nf = 0; nf < 8; nf++) {
                int ncol = nBase + wn * 64 + nf * 8 + tg * 2;
                float b2a = b2[e * Hd + ncol];
                float b2b = b2[e * Hd + ncol + 1];
                #pragma unroll
                for (int h = 0; h < 2; h++) {
                    int row = wm * 32 + mf * 16 + g + h * 8;
                    int slot = mBase + row;
                    if (slot < cnt) {
                        int tok = sv.rowTok[row];
                        float gt = sv.rowGate[row];
                        atomicAdd(&out[(size_t)tok * Hd + ncol],     gt * (acc[mf][nf][h * 2 + 0] + b2a));
                        atomicAdd(&out[(size_t)tok * Hd + ncol + 1], gt * (acc[mf][nf][h * 2 + 1] + b2b));
                    }
                }
            }
        }
    }
}

// ---------------- launch ----------------
extern "C" void kernel_launch(void* const* d_in, const int* in_sizes, int n_in,
                              void* d_out, int out_size)
{
    const float* x  = (const float*)d_in[0];
    const float* ns = (const float*)d_in[1];
    const float* wg = (const float*)d_in[2];
    const float* bg = (const float*)d_in[3];
    const float* w1 = (const float*)d_in[4];
    const float* b1 = (const float*)d_in[5];
    const float* w2 = (const float*)d_in[6];
    const float* b2 = (const float*)d_in[7];
    float* out = (float*)d_out;

    cudaFuncSetAttribute(k_ffn1, cudaFuncAttributeMaxDynamicSharedMemorySize, DYN_SMEM);
    cudaFuncSetAttribute(k_ffn2, cudaFuncAttributeMaxDynamicSharedMemorySize, DYN_SMEM);

    k_norm_route<<<128, 256>>>(x, ns, wg, bg, out);
    k_ffn1<<<dim3(16, 4, 16), 256, DYN_SMEM>>>(w1, b1);
    k_ffn2<<<dim3(8, 4, 16), 256, DYN_SMEM>>>(w2, b2, out);
}

// round 15
// speedup vs baseline: 1.0502x; 1.0502x over previous
#include <cuda_runtime.h>
#include <cuda_fp16.h>
#include <stdint.h>

#define T 1024
#define Hd 1024
#define Id 1024
#define NE 16
#define TOPK 4

// ---------------- scratch (no runtime allocation allowed) ----------------
__device__ __align__(16) __half g_xn[T * Hd];             // normed activations, fp16
__device__ int   g_cnt[NE];
__device__ int   g_perm[NE * T];
__device__ float g_gate[NE * T];
__device__ __align__(16) __half g_s[(size_t)NE * T * Id]; // swiglu output, fp16

// ---------------- shared memory map (ffn kernels) ----------------
#define OFF_A    0
#define OFF_B16  40960
#define OFF_TOK  (40960 + 17408)            // 58368
#define OFF_GATE (58368 + 512)
#define DYN_SMEM (58368 + 1024)             // 59392

#define NORM_SMEM (NE * Hd * 4)             // 65536: transposed wg

// ---------------- kernel 0: count reset ----------------
__global__ void k_zero() { if (threadIdx.x < NE) g_cnt[threadIdx.x] = 0; }

// ---------------- kernel 1: RMSNorm + router + residual (warp-per-token) ----
// grid 128, block 256 (8 warps = 8 tokens). wg is transpose-staged in smem so
// router reads are conflict-free LDS.128 instead of 32-line-splitting LDG.
__global__ __launch_bounds__(256) void k_norm_route(
    const float* __restrict__ x, const float* __restrict__ ns,
    const float* __restrict__ wg, const float* __restrict__ bg,
    float* __restrict__ out)
{
    extern __shared__ float swg[];   // [NE][Hd]

    // transpose-load wg: thread i reads float4 { wg[h][e0..e0+3] }
    for (int i = threadIdx.x; i < Hd * NE / 4; i += 256) {
        float4 v = ((const float4*)wg)[i];
        int h = i >> 2;
        int e0 = (i & 3) * 4;
        swg[(e0 + 0) * Hd + h] = v.x;
        swg[(e0 + 1) * Hd + h] = v.y;
        swg[(e0 + 2) * Hd + h] = v.z;
        swg[(e0 + 3) * Hd + h] = v.w;
    }

    int warp = threadIdx.x >> 5, lane = threadIdx.x & 31;
    int t = blockIdx.x * 8 + warp;

    const float4* xr = (const float4*)(x + (size_t)t * Hd);
    float4 xv[8];
    #pragma unroll
    for (int j = 0; j < 8; j++) xv[j] = xr[j * 32 + lane];

    float ss = 0.f;
    #pragma unroll
    for (int j = 0; j < 8; j++)
        ss += xv[j].x * xv[j].x + xv[j].y * xv[j].y + xv[j].z * xv[j].z + xv[j].w * xv[j].w;
    #pragma unroll
    for (int o = 16; o; o >>= 1) ss += __shfl_xor_sync(0xffffffffu, ss, o);
    float rms = rsqrtf(ss * (1.0f / Hd) + 1e-5f);

    // residual copy + normalize (keep normalized values in registers)
    float4* orow = (float4*)(out + (size_t)t * Hd);
    float4 nrm[8];
    #pragma unroll
    for (int j = 0; j < 8; j++) {
        orow[j * 32 + lane] = xv[j];
        float4 nsv = ((const float4*)ns)[j * 32 + lane];
        nrm[j].x = xv[j].x * rms * nsv.x;
        nrm[j].y = xv[j].y * rms * nsv.y;
        nrm[j].z = xv[j].z * rms * nsv.z;
        nrm[j].w = xv[j].w * rms * nsv.w;
        __half2 p0 = __floats2half2_rn(nrm[j].x, nrm[j].y);
        __half2 p1 = __floats2half2_rn(nrm[j].z, nrm[j].w);
        *(uint2*)(g_xn + (size_t)t * Hd + (j * 32 + lane) * 4) =
            make_uint2(*(uint32_t*)&p0, *(uint32_t*)&p1);
    }

    __syncthreads();   // swg ready

    // router: conflict-free LDS.128 from transposed wg
    float acc[NE];
    #pragma unroll
    for (int e = 0; e < NE; e++) {
        float a = 0.f;
        #pragma unroll
        for (int j = 0; j < 8; j++) {
            float4 wv = *(const float4*)&swg[e * Hd + (j * 32 + lane) * 4];
            a += nrm[j].x * wv.x + nrm[j].y * wv.y + nrm[j].z * wv.z + nrm[j].w * wv.w;
        }
        acc[e] = a;
    }
    #pragma unroll
    for (int o = 16; o; o >>= 1)
        #pragma unroll
        for (int e = 0; e < NE; e++) acc[e] += __shfl_xor_sync(0xffffffffu, acc[e], o);

    if (lane == 0) {
        float logits[NE];
        #pragma unroll
        for (int e = 0; e < NE; e++) logits[e] = acc[e] + bg[e];
        float vals[TOPK]; int idx[TOPK];
        unsigned used = 0;
        for (int k = 0; k < TOPK; k++) {
            float best = -1e30f; int bi = 0;
            #pragma unroll
            for (int e = 0; e < NE; e++)
                if (!((used >> e) & 1u) && logits[e] > best) { best = logits[e]; bi = e; }
            used |= 1u << bi; vals[k] = best; idx[k] = bi;
        }
        float ex[TOPK], den = 0.f;
        #pragma unroll
        for (int k = 0; k < TOPK; k++) { ex[k] = __expf(vals[k] - vals[0]); den += ex[k]; }
        float inv = 1.f / den;
        #pragma unroll
        for (int k = 0; k < TOPK; k++) {
            int e = idx[k];
            int pos = atomicAdd(&g_cnt[e], 1);
            g_perm[e * T + pos] = t;
            g_gate[e * T + pos] = ex[k] * inv;
        }
    }
}

// ---------------- helpers ----------------
__device__ __forceinline__ void mma16816(float* c, const uint32_t* a, const uint32_t* b) {
    asm volatile(
        "mma.sync.aligned.m16n8k16.row.col.f32.f16.f16.f32 "
        "{%0,%1,%2,%3}, {%4,%5,%6,%7}, {%8,%9}, {%0,%1,%2,%3};\n"
        : "+f"(c[0]), "+f"(c[1]), "+f"(c[2]), "+f"(c[3])
        : "r"(a[0]), "r"(a[1]), "r"(a[2]), "r"(a[3]), "r"(b[0]), "r"(b[1]));
}
__device__ __forceinline__ void cpa16(void* dst, const void* src, int sz) {
    uint32_t d = (uint32_t)__cvta_generic_to_shared(dst);
    asm volatile("cp.async.cg.shared.global [%0], [%1], 16, %2;\n" :: "r"(d), "l"(src), "r"(sz));
}
__device__ __forceinline__ void cpa_commit() { asm volatile("cp.async.commit_group;\n"); }
__device__ __forceinline__ void cpa_wait2()  { asm volatile("cp.async.wait_group 2;\n"); }
__device__ __forceinline__ uint32_t h2pack(float a, float b) {
    __half2 h = __floats2half2_rn(a, b);
    return *(uint32_t*)&h;
}
__device__ __forceinline__ void ldsm4(uint32_t* r, const void* p) {
    uint32_t addr = (uint32_t)__cvta_generic_to_shared(p);
    asm volatile("ldmatrix.sync.aligned.m8n8.x4.shared.b16 {%0,%1,%2,%3}, [%4];"
        : "=r"(r[0]), "=r"(r[1]), "=r"(r[2]), "=r"(r[3]) : "r"(addr));
}
__device__ __forceinline__ void ldsm4t(uint32_t* r, const void* p) {
    uint32_t addr = (uint32_t)__cvta_generic_to_shared(p);
    asm volatile("ldmatrix.sync.aligned.m8n8.x4.trans.shared.b16 {%0,%1,%2,%3}, [%4];"
        : "=r"(r[0]), "=r"(r[1]), "=r"(r[2]), "=r"(r[3]) : "r"(addr));
}

struct SmemView {
    __half (*As)[128][40];
    __half (*B16)[32][136];
    int* rowTok;
    float* rowGate;
};
__device__ __forceinline__ SmemView smview(char* base) {
    SmemView s;
    s.As     = (__half(*)[128][40])(base + OFF_A);
    s.B16    = (__half(*)[32][136])(base + OFF_B16);
    s.rowTok = (int*)(base + OFF_TOK);
    s.rowGate= (float*)(base + OFF_GATE);
    return s;
}

__device__ __forceinline__ void ldgB(float4* rF, const float* __restrict__ w,
                                     int ld, int k0, int nBase, int tid) {
    int ck = tid >> 3, l = tid & 7;
    const float* row = w + (size_t)(k0 + ck) * ld + nBase + l * 4;
    #pragma unroll
    for (int j = 0; j < 4; j++) rF[j] = *(const float4*)(row + j * 32);
}
__device__ __forceinline__ void stsB(SmemView& sv, int buf, const float4* rF, int tid) {
    int ck = tid >> 3, l = tid & 7;
    #pragma unroll
    for (int j = 0; j < 4; j++) {
        uint2 p = make_uint2(h2pack(rF[j].x, rF[j].y), h2pack(rF[j].z, rF[j].w));
        *(uint2*)&sv.B16[buf][ck][l * 4 + j * 32] = p;
    }
}

// ---------------- kernel 2: grouped GEMM1 + swiglu ----------------
// grid (nTile=16, mTile=4, expert=16), block 256; warp grid 4x2 (32m x 64n)
__global__ __launch_bounds__(256, 2) void k_ffn1(
    const float* __restrict__ w1, const float* __restrict__ b1)
{
    extern __shared__ char smbase[];
    SmemView sv = smview(smbase);

    int e = blockIdx.z;
    int cnt = g_cnt[e];
    int mBase = blockIdx.y * 128;
    if (mBase >= cnt) return;
    int nBase = blockIdx.x * 128;
    int validRows = cnt - mBase; if (validRows > 128) validRows = 128;

    int tid = threadIdx.x;
    if (tid < 128) {
        int slot = mBase + tid;
        sv.rowTok[tid] = (slot < cnt) ? g_perm[e * T + slot] : -1;
    }
    __syncthreads();

    int lane = tid & 31, warp = tid >> 5;
    int wm = warp >> 1, wn = warp & 1;
    bool warpLive = (wm * 32) < validRows;

    float acc[2][8][4];
    #pragma unroll
    for (int mf = 0; mf < 2; mf++)
        #pragma unroll
        for (int nf = 0; nf < 8; nf++)
            #pragma unroll
            for (int i = 0; i < 4; i++) acc[mf][nf][i] = 0.f;

    auto issueA = [&](int s) {
        int k0 = s * 32;
        #pragma unroll
        for (int c = 0; c < 2; c++) {
            int ch = tid + c * 256;
            int row = ch >> 2, col = (ch & 3) * 8;
            int tok = sv.rowTok[row];
            if (tok >= 0) cpa16(&sv.As[s & 3][row][col], g_xn + (size_t)tok * Hd + k0 + col, 16);
            else          cpa16(&sv.As[s & 3][row][col], g_xn, 0);
        }
    };

    const int LD = 2 * Id;
    float4 rF[4];

    issueA(0); cpa_commit();
    issueA(1); cpa_commit();
    issueA(2); cpa_commit();
    ldgB(rF, w1 + (size_t)e * Hd * LD, LD, 0, nBase, tid);
    stsB(sv, 0, rF, tid);
    ldgB(rF, w1 + (size_t)e * Hd * LD, LD, 32, nBase, tid);

    const int KT = Hd / 32;
    for (int it = 0; it < KT; it++) {
        cpa_wait2();
        __syncthreads();
        if (it + 1 < KT) stsB(sv, (it + 1) & 1, rF, tid);
        if (warpLive) {
            #pragma unroll
            for (int kk = 0; kk < 32; kk += 16) {
                uint32_t a[2][4], b[8][2];
                #pragma unroll
                for (int mf = 0; mf < 2; mf++) {
                    int r = wm * 32 + mf * 16 + (lane & 15);
                    ldsm4(a[mf], &sv.As[it & 3][r][kk + (lane >> 4) * 8]);
                }
                #pragma unroll
                for (int pair = 0; pair < 4; pair++) {
                    int m = lane >> 3, r = lane & 7;
                    uint32_t rr[4];
                    ldsm4t(rr, &sv.B16[it & 1][kk + (m & 1) * 8 + r][wn * 64 + pair * 16 + (m >> 1) * 8]);
                    b[pair * 2 + 0][0] = rr[0]; b[pair * 2 + 0][1] = rr[1];
                    b[pair * 2 + 1][0] = rr[2]; b[pair * 2 + 1][1] = rr[3];
                }
                #pragma unroll
                for (int mf = 0; mf < 2; mf++)
                    #pragma unroll
                    for (int nf = 0; nf < 8; nf++)
                        mma16816(acc[mf][nf], a[mf], b[nf]);
            }
        }
        if (it + 2 < KT) ldgB(rF, w1 + (size_t)e * Hd * LD, LD, (it + 2) * 32, nBase, tid);
        if (it + 3 < KT) issueA(it + 3);
        cpa_commit();
    }

    // ---- epilogue: swiglu -> smem staging -> coalesced g_s ----
    __half (*Ss)[72] = (__half(*)[72])(smbase + OFF_A);
    __syncthreads();
    if (warpLive) {
        int g = lane >> 2, tg = lane & 3;
        #pragma unroll
        for (int mf = 0; mf < 2; mf++) {
            #pragma unroll
            for (int nf = 0; nf < 8; nf++) {
                int ncol = nBase + wn * 64 + nf * 8 + tg * 2;   // even
                float ba = b1[e * (2 * Id) + ncol];
                float bb = b1[e * (2 * Id) + ncol + 1];
                int sl = wn * 32 + nf * 4 + tg;                 // local scol 0..63
                #pragma unroll
                for (int h = 0; h < 2; h++) {
                    int row = wm * 32 + mf * 16 + g + h * 8;
                    float av = acc[mf][nf][h * 2 + 0] + ba;
                    float bv = acc[mf][nf][h * 2 + 1] + bb;
                    av = fminf(av, 7.0f);
                    bv = fminf(fmaxf(bv, -7.0f), 7.0f);
                    float sig = __frcp_rn(1.f + __expf(-1.702f * av));
                    Ss[row][sl] = __float2half(av * sig * (bv + 1.f));
                }
            }
        }
    }
    __syncthreads();
    {
        int r0 = tid >> 3, cl = (tid & 7) * 8;
        #pragma unroll
        for (int p = 0; p < 4; p++) {
            int row = p * 32 + r0;
            int slot = mBase + row;
            if (slot < cnt) {
                uint4 v = *(uint4*)&Ss[row][cl];
                *(uint4*)(g_s + ((size_t)(e * T + slot)) * Id + (nBase >> 1) + cl) = v;
            }
        }
    }
}

// ---------------- kernel 3: grouped GEMM2 + gated scatter ----------------
// grid (nTile=8, mTile=4, expert=16), block 256; warp grid 4x2
__global__ __launch_bounds__(256, 2) void k_ffn2(
    const float* __restrict__ w2, const float* __restrict__ b2, float* __restrict__ out)
{
    extern __shared__ char smbase[];
    SmemView sv = smview(smbase);

    int e = blockIdx.z;
    int cnt = g_cnt[e];
    int mBase = blockIdx.y * 128;
    if (mBase >= cnt) return;
    int nBase = blockIdx.x * 128;
    int validRows = cnt - mBase; if (validRows > 128) validRows = 128;

    int tid = threadIdx.x;
    if (tid < 128) {
        int slot = mBase + tid;
        if (slot < cnt) { sv.rowTok[tid] = g_perm[e * T + slot]; sv.rowGate[tid] = g_gate[e * T + slot]; }
        else            { sv.rowTok[tid] = -1;                   sv.rowGate[tid] = 0.f; }
    }
    __syncthreads();

    int lane = tid & 31, warp = tid >> 5;
    int wm = warp >> 1, wn = warp & 1;
    bool warpLive = (wm * 32) < validRows;

    float acc[2][8][4];
    #pragma unroll
    for (int mf = 0; mf < 2; mf++)
        #pragma unroll
        for (int nf = 0; nf < 8; nf++)
            #pragma unroll
            for (int i = 0; i < 4; i++) acc[mf][nf][i] = 0.f;

    auto issueA = [&](int s) {
        int k0 = s * 32;
        #pragma unroll
        for (int c = 0; c < 2; c++) {
            int ch = tid + c * 256;
            int row = ch >> 2, col = (ch & 3) * 8;
            int valid = (row < validRows) ? 16 : 0;
            const __half* src = g_s + ((size_t)(e * T + mBase + row)) * Id + k0 + col;
            cpa16(&sv.As[s & 3][row][col], src, valid);
        }
    };

    float4 rF[4];

    issueA(0); cpa_commit();
    issueA(1); cpa_commit();
    issueA(2); cpa_commit();
    ldgB(rF, w2 + (size_t)e * Id * Hd, Hd, 0, nBase, tid);
    stsB(sv, 0, rF, tid);
    ldgB(rF, w2 + (size_t)e * Id * Hd, Hd, 32, nBase, tid);

    const int KT = Id / 32;
    for (int it = 0; it < KT; it++) {
        cpa_wait2();
        __syncthreads();
        if (it + 1 < KT) stsB(sv, (it + 1) & 1, rF, tid);
        if (warpLive) {
            #pragma unroll
            for (int kk = 0; kk < 32; kk += 16) {
                uint32_t a[2][4], b[8][2];
                #pragma unroll
                for (int mf = 0; mf < 2; mf++) {
                    int r = wm * 32 + mf * 16 + (lane & 15);
                    ldsm4(a[mf], &sv.As[it & 3][r][kk + (lane >> 4) * 8]);
                }
                #pragma unroll
                for (int pair = 0; pair < 4; pair++) {
                    int m = lane >> 3, r = lane & 7;
                    uint32_t rr[4];
                    ldsm4t(rr, &sv.B16[it & 1][kk + (m & 1) * 8 + r][wn * 64 + pair * 16 + (m >> 1) * 8]);
                    b[pair * 2 + 0][0] = rr[0]; b[pair * 2 + 0][1] = rr[1];
                    b[pair * 2 + 1][0] = rr[2]; b[pair * 2 + 1][1] = rr[3];
                }
                #pragma unroll
                for (int mf = 0; mf < 2; mf++)
                    #pragma unroll
                    for (int nf = 0; nf < 8; nf++)
                        mma16816(acc[mf][nf], a[mf], b[nf]);
            }
        }
        if (it + 2 < KT) ldgB(rF, w2 + (size_t)e * Id * Hd, Hd, (it + 2) * 32, nBase, tid);
        if (it + 3 < KT) issueA(it + 3);
        cpa_commit();
    }

    if (warpLive) {
        int g = lane >> 2, tg = lane & 3;
        #pragma unroll
        for (int mf = 0; mf < 2; mf++) {
            #pragma unroll
            for (int nf = 0; nf < 8; nf++) {
                int ncol = nBase + wn * 64 + nf * 8 + tg * 2;
                float b2a = b2[e * Hd + ncol];
                float b2b = b2[e * Hd + ncol + 1];
                #pragma unroll
                for (int h = 0; h < 2; h++) {
                    int row = wm * 32 + mf * 16 + g + h * 8;
                    int slot = mBase + row;
                    if (slot < cnt) {
                        int tok = sv.rowTok[row];
                        float gt = sv.rowGate[row];
                        atomicAdd(&out[(size_t)tok * Hd + ncol],     gt * (acc[mf][nf][h * 2 + 0] + b2a));
                        atomicAdd(&out[(size_t)tok * Hd + ncol + 1], gt * (acc[mf][nf][h * 2 + 1] + b2b));
                    }
                }
            }
        }
    }
}

// ---------------- launch ----------------
extern "C" void kernel_launch(void* const* d_in, const int* in_sizes, int n_in,
                              void* d_out, int out_size)
{
    const float* x  = (const float*)d_in[0];
    const float* ns = (const float*)d_in[1];
    const float* wg = (const float*)d_in[2];
    const float* bg = (const float*)d_in[3];
    const float* w1 = (const float*)d_in[4];
    const float* b1 = (const float*)d_in[5];
    const float* w2 = (const float*)d_in[6];
    const float* b2 = (const float*)d_in[7];
    float* out = (float*)d_out;

    cudaFuncSetAttribute(k_norm_route, cudaFuncAttributeMaxDynamicSharedMemorySize, NORM_SMEM);
    cudaFuncSetAttribute(k_ffn1, cudaFuncAttributeMaxDynamicSharedMemorySize, DYN_SMEM);
    cudaFuncSetAttribute(k_ffn2, cudaFuncAttributeMaxDynamicSharedMemorySize, DYN_SMEM);

    k_zero<<<1, 32>>>();
    k_norm_route<<<128, 256, NORM_SMEM>>>(x, ns, wg, bg, out);
    k_ffn1<<<dim3(16, 4, 16), 256, DYN_SMEM>>>(w1, b1);
    k_ffn2<<<dim3(8, 4, 16), 256, DYN_SMEM>>>(w2, b2, out);
}

// round 16
// speedup vs baseline: 1.0526x; 1.0023x over previous
#include <cuda_runtime.h>
#include <cuda_fp16.h>
#include <stdint.h>

#define T 1024
#define Hd 1024
#define Id 1024
#define NE 16
#define TOPK 4

// ---------------- scratch (no runtime allocation allowed) ----------------
__device__ __align__(16) __half g_xn[T * Hd];             // normed activations, fp16
__device__ int   g_cnt[NE];
__device__ int   g_perm[NE * T];
__device__ float g_gate[NE * T];
__device__ int   g_flag;                                  // counters-zeroed flag
__device__ __align__(16) __half g_s[(size_t)NE * T * Id]; // swiglu output, fp16

// ---------------- shared memory map (ffn kernels) ----------------
#define OFF_A    0
#define OFF_B16  40960
#define OFF_TOK  (40960 + 17408)            // 58368
#define OFF_GATE (58368 + 512)
#define DYN_SMEM (58368 + 1024)             // 59392

#define NORM_SMEM (NE * Hd * 4)             // 65536: transposed wg

// ---------------- kernel 1: RMSNorm + router + residual (warp-per-token) ----
// grid 128, block 256 (8 warps = 8 tokens). wg transpose-staged in smem.
// Block 0 zeroes g_cnt then raises g_flag; lane-0 threads spin on it before
// their atomicAdds (block 0 raises it ~immediately; others arrive ~us later).
// g_flag is reset by k_ffn1 CTA(0,0,0) -> deterministic across graph replays.
__global__ __launch_bounds__(256) void k_norm_route(
    const float* __restrict__ x, const float* __restrict__ ns,
    const float* __restrict__ wg, const float* __restrict__ bg,
    float* __restrict__ out)
{
    extern __shared__ float swg[];   // [NE][Hd]

    if (blockIdx.x == 0 && threadIdx.x < 32) {
        if (threadIdx.x < NE) g_cnt[threadIdx.x] = 0;
        __threadfence();
        __syncwarp();
        if (threadIdx.x == 0) atomicExch(&g_flag, 1);
    }

    // transpose-load wg: thread i reads float4 { wg[h][e0..e0+3] }
    for (int i = threadIdx.x; i < Hd * NE / 4; i += 256) {
        float4 v = ((const float4*)wg)[i];
        int h = i >> 2;
        int e0 = (i & 3) * 4;
        swg[(e0 + 0) * Hd + h] = v.x;
        swg[(e0 + 1) * Hd + h] = v.y;
        swg[(e0 + 2) * Hd + h] = v.z;
        swg[(e0 + 3) * Hd + h] = v.w;
    }

    int warp = threadIdx.x >> 5, lane = threadIdx.x & 31;
    int t = blockIdx.x * 8 + warp;

    const float4* xr = (const float4*)(x + (size_t)t * Hd);
    float4 xv[8];
    #pragma unroll
    for (int j = 0; j < 8; j++) xv[j] = xr[j * 32 + lane];

    float ss = 0.f;
    #pragma unroll
    for (int j = 0; j < 8; j++)
        ss += xv[j].x * xv[j].x + xv[j].y * xv[j].y + xv[j].z * xv[j].z + xv[j].w * xv[j].w;
    #pragma unroll
    for (int o = 16; o; o >>= 1) ss += __shfl_xor_sync(0xffffffffu, ss, o);
    float rms = rsqrtf(ss * (1.0f / Hd) + 1e-5f);

    // residual copy + normalize (keep normalized values in registers)
    float4* orow = (float4*)(out + (size_t)t * Hd);
    float4 nrm[8];
    #pragma unroll
    for (int j = 0; j < 8; j++) {
        orow[j * 32 + lane] = xv[j];
        float4 nsv = ((const float4*)ns)[j * 32 + lane];
        nrm[j].x = xv[j].x * rms * nsv.x;
        nrm[j].y = xv[j].y * rms * nsv.y;
        nrm[j].z = xv[j].z * rms * nsv.z;
        nrm[j].w = xv[j].w * rms * nsv.w;
        __half2 p0 = __floats2half2_rn(nrm[j].x, nrm[j].y);
        __half2 p1 = __floats2half2_rn(nrm[j].z, nrm[j].w);
        *(uint2*)(g_xn + (size_t)t * Hd + (j * 32 + lane) * 4) =
            make_uint2(*(uint32_t*)&p0, *(uint32_t*)&p1);
    }

    __syncthreads();   // swg ready

    // router: conflict-free LDS.128 from transposed wg
    float acc[NE];
    #pragma unroll
    for (int e = 0; e < NE; e++) {
        float a = 0.f;
        #pragma unroll
        for (int j = 0; j < 8; j++) {
            float4 wv = *(const float4*)&swg[e * Hd + (j * 32 + lane) * 4];
            a += nrm[j].x * wv.x + nrm[j].y * wv.y + nrm[j].z * wv.z + nrm[j].w * wv.w;
        }
        acc[e] = a;
    }
    #pragma unroll
    for (int o = 16; o; o >>= 1)
        #pragma unroll
        for (int e = 0; e < NE; e++) acc[e] += __shfl_xor_sync(0xffffffffu, acc[e], o);

    if (lane == 0) {
        float logits[NE];
        #pragma unroll
        for (int e = 0; e < NE; e++) logits[e] = acc[e] + bg[e];
        float vals[TOPK]; int idx[TOPK];
        unsigned used = 0;
        for (int k = 0; k < TOPK; k++) {
            float best = -1e30f; int bi = 0;
            #pragma unroll
            for (int e = 0; e < NE; e++)
                if (!((used >> e) & 1u) && logits[e] > best) { best = logits[e]; bi = e; }
            used |= 1u << bi; vals[k] = best; idx[k] = bi;
        }
        float ex[TOPK], den = 0.f;
        #pragma unroll
        for (int k = 0; k < TOPK; k++) { ex[k] = __expf(vals[k] - vals[0]); den += ex[k]; }
        float inv = 1.f / den;
        // counters guaranteed zeroed once g_flag is up
        {
            volatile int* fp = &g_flag;
            while (*fp == 0) { }
        }
        #pragma unroll
        for (int k = 0; k < TOPK; k++) {
            int e = idx[k];
            int pos = atomicAdd(&g_cnt[e], 1);
            g_perm[e * T + pos] = t;
            g_gate[e * T + pos] = ex[k] * inv;
        }
    }
}

// ---------------- helpers ----------------
__device__ __forceinline__ void mma16816(float* c, const uint32_t* a, const uint32_t* b) {
    asm volatile(
        "mma.sync.aligned.m16n8k16.row.col.f32.f16.f16.f32 "
        "{%0,%1,%2,%3}, {%4,%5,%6,%7}, {%8,%9}, {%0,%1,%2,%3};\n"
        : "+f"(c[0]), "+f"(c[1]), "+f"(c[2]), "+f"(c[3])
        : "r"(a[0]), "r"(a[1]), "r"(a[2]), "r"(a[3]), "r"(b[0]), "r"(b[1]));
}
__device__ __forceinline__ void cpa16(void* dst, const void* src, int sz) {
    uint32_t d = (uint32_t)__cvta_generic_to_shared(dst);
    asm volatile("cp.async.cg.shared.global [%0], [%1], 16, %2;\n" :: "r"(d), "l"(src), "r"(sz));
}
__device__ __forceinline__ void cpa_commit() { asm volatile("cp.async.commit_group;\n"); }
__device__ __forceinline__ void cpa_wait2()  { asm volatile("cp.async.wait_group 2;\n"); }
__device__ __forceinline__ uint32_t h2pack(float a, float b) {
    __half2 h = __floats2half2_rn(a, b);
    return *(uint32_t*)&h;
}
__device__ __forceinline__ void ldsm4(uint32_t* r, const void* p) {
    uint32_t addr = (uint32_t)__cvta_generic_to_shared(p);
    asm volatile("ldmatrix.sync.aligned.m8n8.x4.shared.b16 {%0,%1,%2,%3}, [%4];"
        : "=r"(r[0]), "=r"(r[1]), "=r"(r[2]), "=r"(r[3]) : "r"(addr));
}
__device__ __forceinline__ void ldsm4t(uint32_t* r, const void* p) {
    uint32_t addr = (uint32_t)__cvta_generic_to_shared(p);
    asm volatile("ldmatrix.sync.aligned.m8n8.x4.trans.shared.b16 {%0,%1,%2,%3}, [%4];"
        : "=r"(r[0]), "=r"(r[1]), "=r"(r[2]), "=r"(r[3]) : "r"(addr));
}
__device__ __forceinline__ void red2(float* p, float a, float b) {
    asm volatile("red.global.add.v2.f32 [%0], {%1, %2};" :: "l"(p), "f"(a), "f"(b) : "memory");
}

struct SmemView {
    __half (*As)[128][40];
    __half (*B16)[32][136];
    int* rowTok;
    float* rowGate;
};
__device__ __forceinline__ SmemView smview(char* base) {
    SmemView s;
    s.As     = (__half(*)[128][40])(base + OFF_A);
    s.B16    = (__half(*)[32][136])(base + OFF_B16);
    s.rowTok = (int*)(base + OFF_TOK);
    s.rowGate= (float*)(base + OFF_GATE);
    return s;
}

__device__ __forceinline__ void ldgB(float4* rF, const float* __restrict__ w,
                                     int ld, int k0, int nBase, int tid) {
    int ck = tid >> 3, l = tid & 7;
    const float* row = w + (size_t)(k0 + ck) * ld + nBase + l * 4;
    #pragma unroll
    for (int j = 0; j < 4; j++) rF[j] = *(const float4*)(row + j * 32);
}
__device__ __forceinline__ void stsB(SmemView& sv, int buf, const float4* rF, int tid) {
    int ck = tid >> 3, l = tid & 7;
    #pragma unroll
    for (int j = 0; j < 4; j++) {
        uint2 p = make_uint2(h2pack(rF[j].x, rF[j].y), h2pack(rF[j].z, rF[j].w));
        *(uint2*)&sv.B16[buf][ck][l * 4 + j * 32] = p;
    }
}

// ---------------- kernel 2: grouped GEMM1 + swiglu ----------------
// grid (nTile=16, mTile=4, expert=16), block 256; warp grid 4x2 (32m x 64n)
__global__ __launch_bounds__(256, 2) void k_ffn1(
    const float* __restrict__ w1, const float* __restrict__ b1)
{
    extern __shared__ char smbase[];
    SmemView sv = smview(smbase);

    // reset the norm-kernel flag for the next graph replay (norm is complete
    // by stream order, so this is race-free). Unconditional: before early-out.
    if (blockIdx.x == 0 && blockIdx.y == 0 && blockIdx.z == 0 && threadIdx.x == 0)
        g_flag = 0;

    int e = blockIdx.z;
    int cnt = g_cnt[e];
    int mBase = blockIdx.y * 128;
    if (mBase >= cnt) return;
    int nBase = blockIdx.x * 128;
    int validRows = cnt - mBase; if (validRows > 128) validRows = 128;

    int tid = threadIdx.x;
    if (tid < 128) {
        int slot = mBase + tid;
        sv.rowTok[tid] = (slot < cnt) ? g_perm[e * T + slot] : -1;
    }
    __syncthreads();

    int lane = tid & 31, warp = tid >> 5;
    int wm = warp >> 1, wn = warp & 1;
    bool warpLive = (wm * 32) < validRows;

    float acc[2][8][4];
    #pragma unroll
    for (int mf = 0; mf < 2; mf++)
        #pragma unroll
        for (int nf = 0; nf < 8; nf++)
            #pragma unroll
            for (int i = 0; i < 4; i++) acc[mf][nf][i] = 0.f;

    auto issueA = [&](int s) {
        int k0 = s * 32;
        #pragma unroll
        for (int c = 0; c < 2; c++) {
            int ch = tid + c * 256;
            int row = ch >> 2, col = (ch & 3) * 8;
            int tok = sv.rowTok[row];
            if (tok >= 0) cpa16(&sv.As[s & 3][row][col], g_xn + (size_t)tok * Hd + k0 + col, 16);
            else          cpa16(&sv.As[s & 3][row][col], g_xn, 0);
        }
    };

    const int LD = 2 * Id;
    float4 rF[4];

    issueA(0); cpa_commit();
    issueA(1); cpa_commit();
    issueA(2); cpa_commit();
    ldgB(rF, w1 + (size_t)e * Hd * LD, LD, 0, nBase, tid);
    stsB(sv, 0, rF, tid);
    ldgB(rF, w1 + (size_t)e * Hd * LD, LD, 32, nBase, tid);

    const int KT = Hd / 32;
    for (int it = 0; it < KT; it++) {
        cpa_wait2();
        __syncthreads();
        if (it + 1 < KT) stsB(sv, (it + 1) & 1, rF, tid);
        if (warpLive) {
            #pragma unroll
            for (int kk = 0; kk < 32; kk += 16) {
                uint32_t a[2][4], b[8][2];
                #pragma unroll
                for (int mf = 0; mf < 2; mf++) {
                    int r = wm * 32 + mf * 16 + (lane & 15);
                    ldsm4(a[mf], &sv.As[it & 3][r][kk + (lane >> 4) * 8]);
                }
                #pragma unroll
                for (int pair = 0; pair < 4; pair++) {
                    int m = lane >> 3, r = lane & 7;
                    uint32_t rr[4];
                    ldsm4t(rr, &sv.B16[it & 1][kk + (m & 1) * 8 + r][wn * 64 + pair * 16 + (m >> 1) * 8]);
                    b[pair * 2 + 0][0] = rr[0]; b[pair * 2 + 0][1] = rr[1];
                    b[pair * 2 + 1][0] = rr[2]; b[pair * 2 + 1][1] = rr[3];
                }
                #pragma unroll
                for (int mf = 0; mf < 2; mf++)
                    #pragma unroll
                    for (int nf = 0; nf < 8; nf++)
                        mma16816(acc[mf][nf], a[mf], b[nf]);
            }
        }
        if (it + 2 < KT) ldgB(rF, w1 + (size_t)e * Hd * LD, LD, (it + 2) * 32, nBase, tid);
        if (it + 3 < KT) issueA(it + 3);
        cpa_commit();
    }

    // ---- epilogue: swiglu -> smem staging -> coalesced g_s ----
    __half (*Ss)[72] = (__half(*)[72])(smbase + OFF_A);
    __syncthreads();
    if (warpLive) {
        int g = lane >> 2, tg = lane & 3;
        #pragma unroll
        for (int mf = 0; mf < 2; mf++) {
            #pragma unroll
            for (int nf = 0; nf < 8; nf++) {
                int ncol = nBase + wn * 64 + nf * 8 + tg * 2;   // even
                float ba = b1[e * (2 * Id) + ncol];
                float bb = b1[e * (2 * Id) + ncol + 1];
                int sl = wn * 32 + nf * 4 + tg;                 // local scol 0..63
                #pragma unroll
                for (int h = 0; h < 2; h++) {
                    int row = wm * 32 + mf * 16 + g + h * 8;
                    float av = acc[mf][nf][h * 2 + 0] + ba;
                    float bv = acc[mf][nf][h * 2 + 1] + bb;
                    av = fminf(av, 7.0f);
                    bv = fminf(fmaxf(bv, -7.0f), 7.0f);
                    float sig = __frcp_rn(1.f + __expf(-1.702f * av));
                    Ss[row][sl] = __float2half(av * sig * (bv + 1.f));
                }
            }
        }
    }
    __syncthreads();
    {
        int r0 = tid >> 3, cl = (tid & 7) * 8;
        #pragma unroll
        for (int p = 0; p < 4; p++) {
            int row = p * 32 + r0;
            int slot = mBase + row;
            if (slot < cnt) {
                uint4 v = *(uint4*)&Ss[row][cl];
                *(uint4*)(g_s + ((size_t)(e * T + slot)) * Id + (nBase >> 1) + cl) = v;
            }
        }
    }
}

// ---------------- kernel 3: grouped GEMM2 + gated scatter ----------------
// grid (nTile=8, mTile=4, expert=16), block 256; warp grid 4x2
__global__ __launch_bounds__(256, 2) void k_ffn2(
    const float* __restrict__ w2, const float* __restrict__ b2, float* __restrict__ out)
{
    extern __shared__ char smbase[];
    SmemView sv = smview(smbase);

    int e = blockIdx.z;
    int cnt = g_cnt[e];
    int mBase = blockIdx.y * 128;
    if (mBase >= cnt) return;
    int nBase = blockIdx.x * 128;
    int validRows = cnt - mBase; if (validRows > 128) validRows = 128;

    int tid = threadIdx.x;
    if (tid < 128) {
        int slot = mBase + tid;
        if (slot < cnt) { sv.rowTok[tid] = g_perm[e * T + slot]; sv.rowGate[tid] = g_gate[e * T + slot]; }
        else            { sv.rowTok[tid] = -1;                   sv.rowGate[tid] = 0.f; }
    }
    __syncthreads();

    int lane = tid & 31, warp = tid >> 5;
    int wm = warp >> 1, wn = warp & 1;
    bool warpLive = (wm * 32) < validRows;

    float acc[2][8][4];
    #pragma unroll
    for (int mf = 0; mf < 2; mf++)
        #pragma unroll
        for (int nf = 0; nf < 8; nf++)
            #pragma unroll
            for (int i = 0; i < 4; i++) acc[mf][nf][i] = 0.f;

    auto issueA = [&](int s) {
        int k0 = s * 32;
        #pragma unroll
        for (int c = 0; c < 2; c++) {
            int ch = tid + c * 256;
            int row = ch >> 2, col = (ch & 3) * 8;
            int valid = (row < validRows) ? 16 : 0;
            const __half* src = g_s + ((size_t)(e * T + mBase + row)) * Id + k0 + col;
            cpa16(&sv.As[s & 3][row][col], src, valid);
        }
    };

    float4 rF[4];

    issueA(0); cpa_commit();
    issueA(1); cpa_commit();
    issueA(2); cpa_commit();
    ldgB(rF, w2 + (size_t)e * Id * Hd, Hd, 0, nBase, tid);
    stsB(sv, 0, rF, tid);
    ldgB(rF, w2 + (size_t)e * Id * Hd, Hd, 32, nBase, tid);

    const int KT = Id / 32;
    for (int it = 0; it < KT; it++) {
        cpa_wait2();
        __syncthreads();
        if (it + 1 < KT) stsB(sv, (it + 1) & 1, rF, tid);
        if (warpLive) {
            #pragma unroll
            for (int kk = 0; kk < 32; kk += 16) {
                uint32_t a[2][4], b[8][2];
                #pragma unroll
                for (int mf = 0; mf < 2; mf++) {
                    int r = wm * 32 + mf * 16 + (lane & 15);
                    ldsm4(a[mf], &sv.As[it & 3][r][kk + (lane >> 4) * 8]);
                }
                #pragma unroll
                for (int pair = 0; pair < 4; pair++) {
                    int m = lane >> 3, r = lane & 7;
                    uint32_t rr[4];
                    ldsm4t(rr, &sv.B16[it & 1][kk + (m & 1) * 8 + r][wn * 64 + pair * 16 + (m >> 1) * 8]);
                    b[pair * 2 + 0][0] = rr[0]; b[pair * 2 + 0][1] = rr[1];
                    b[pair * 2 + 1][0] = rr[2]; b[pair * 2 + 1][1] = rr[3];
                }
                #pragma unroll
                for (int mf = 0; mf < 2; mf++)
                    #pragma unroll
                    for (int nf = 0; nf < 8; nf++)
                        mma16816(acc[mf][nf], a[mf], b[nf]);
            }
        }
        if (it + 2 < KT) ldgB(rF, w2 + (size_t)e * Id * Hd, Hd, (it + 2) * 32, nBase, tid);
        if (it + 3 < KT) issueA(it + 3);
        cpa_commit();
    }

    if (warpLive) {
        int g = lane >> 2, tg = lane & 3;
        #pragma unroll
        for (int mf = 0; mf < 2; mf++) {
            #pragma unroll
            for (int nf = 0; nf < 8; nf++) {
                int ncol = nBase + wn * 64 + nf * 8 + tg * 2;
                float b2a = b2[e * Hd + ncol];
                float b2b = b2[e * Hd + ncol + 1];
                #pragma unroll
                for (int h = 0; h < 2; h++) {
                    int row = wm * 32 + mf * 16 + g + h * 8;
                    int slot = mBase + row;
                    if (slot < cnt) {
                        int tok = sv.rowTok[row];
                        float gt = sv.rowGate[row];
                        red2(&out[(size_t)tok * Hd + ncol],
                             gt * (acc[mf][nf][h * 2 + 0] + b2a),
                             gt * (acc[mf][nf][h * 2 + 1] + b2b));
                    }
                }
            }
        }
    }
}

// ---------------- launch ----------------
extern "C" void kernel_launch(void* const* d_in, const int* in_sizes, int n_in,
                              void* d_out, int out_size)
{
    const float* x  = (const float*)d_in[0];
    const float* ns = (const float*)d_in[1];
    const float* wg = (const float*)d_in[2];
    const float* bg = (const float*)d_in[3];
    const float* w1 = (const float*)d_in[4];
    const float* b1 = (const float*)d_in[5];
    const float* w2 = (const float*)d_in[6];
    const float* b2 = (const float*)d_in[7];
    float* out = (float*)d_out;

    cudaFuncSetAttribute(k_norm_route, cudaFuncAttributeMaxDynamicSharedMemorySize, NORM_SMEM);
    cudaFuncSetAttribute(k_ffn1, cudaFuncAttributeMaxDynamicSharedMemorySize, DYN_SMEM);
    cudaFuncSetAttribute(k_ffn2, cudaFuncAttributeMaxDynamicSharedMemorySize, DYN_SMEM);

    k_norm_route<<<128, 256, NORM_SMEM>>>(x, ns, wg, bg, out);
    k_ffn1<<<dim3(16, 4, 16), 256, DYN_SMEM>>>(w1, b1);
    k_ffn2<<<dim3(8, 4, 16), 256, DYN_SMEM>>>(w2, b2, out);
}